// round 9
// baseline (speedup 1.0000x reference)
#include <cuda_runtime.h>
#include <cstdint>
#include <climits>

#define Bc 4
#define Fc 60082
#define Cc 14695
#define Dc 256
#define KNc 64
#define KHc 128
#define NTH 8                    // his slots per his block (256 threads)
#define MROWS 32                 // field rows per dense block (4 stages of 8)
#define NMAIN ((Fc + MROWS - 1) / MROWS)   // 1878 dense blocks
#define NHIS ((Bc*KHc)/NTH)      // 64 his blocks
#define NCORR ((KNc + KHc) / 8 * Bc)       // 96 corr blocks

// Scratch (no allocation allowed) — __device__ globals.
__device__ __align__(16) float g_u[Dc];   // W_proj @ w_ff
__device__ float g_comp[Bc];              // company_mem . w_fc + b_fc
__device__ float g_c0;                    // b_proj . w_ff
__device__ float g_hisdot[Bc*KHc];        // leaky(rfe@W1+b1).w2v + c2 per his slot
__device__ int   g_done;                  // dense-blocks-finished counter

__device__ __forceinline__ float warp_sum(float v) {
    v += __shfl_xor_sync(0xffffffffu, v, 16);
    v += __shfl_xor_sync(0xffffffffu, v, 8);
    v += __shfl_xor_sync(0xffffffffu, v, 4);
    v += __shfl_xor_sync(0xffffffffu, v, 2);
    v += __shfl_xor_sync(0xffffffffu, v, 1);
    return v;
}

__device__ __forceinline__ float dot8(const float* __restrict__ a, const float* __restrict__ b) {
    float4 a0 = ((const float4*)a)[0], a1 = ((const float4*)a)[1];
    float4 b0 = ((const float4*)b)[0], b1 = ((const float4*)b)[1];
    return a0.x*b0.x + a0.y*b0.y + a0.z*b0.z + a0.w*b0.w
         + a1.x*b1.x + a1.y*b1.y + a1.z*b1.z + a1.w*b1.w;
}

// ===========================================================================
// Kernel A: his-MLP blocks (0..63) + prep blocks (64..96), 256 threads each.
// (Round-5 configuration, measured best.)
// ===========================================================================
__global__ void __launch_bounds__(256) hisprep_kernel(
                           const float* __restrict__ raw_field_embed,
                           const float* __restrict__ W1,
                           const float* __restrict__ b1,
                           const float* __restrict__ W2,
                           const float* __restrict__ b2,
                           const float* __restrict__ w_ff,
                           const float* __restrict__ company_emb,
                           const float* __restrict__ comp_table,
                           const float* __restrict__ W_proj,
                           const float* __restrict__ b_proj,
                           const float* __restrict__ theta,
                           const float* __restrict__ w_fc,
                           const float* __restrict__ b_fc,
                           const int*   __restrict__ com_id,
                           const int*   __restrict__ his_nodes)
{
    int t = threadIdx.x;
    int warp = t >> 5, lane = t & 31;

    if (blockIdx.x < NHIS) {
        __shared__ __align__(16) float rfe[NTH][Dc];   // 8 KB
        __shared__ float red[8][4];
        __shared__ float w2v_s[Dc/2];
        __shared__ float c2_s;
        int j = t & 127, h = t >> 7;
        int slot0 = blockIdx.x * NTH;

        #pragma unroll
        for (int i = t; i < NTH*Dc/4; i += 256) {
            int n  = i >> 6;
            int c4 = i & 63;
            int f  = his_nodes[slot0 + n];
            ((float4*)rfe[n])[c4] = ((const float4*)(raw_field_embed + (size_t)f*Dc))[c4];
        }
        #pragma unroll
        for (int r = 0; r < 16; r++) {
            int jr = warp * 16 + r;
            float s = warp_sum(dot8(W2 + (size_t)jr*Dc + lane*8, w_ff + lane*8));
            if (lane == 0) w2v_s[jr] = s;
        }
        if (warp == 0) {
            float s = warp_sum(dot8(b2 + lane*8, w_ff + lane*8));
            if (lane == 0) c2_s = s;
        }
        __syncthreads();

        float bj = b1[j];
        float acc0 = bj, acc1 = bj, acc2 = bj, acc3 = bj;
        int nb = h * 4;
        #pragma unroll 4
        for (int k = 0; k < Dc; k += 4) {
            float wa = W1[(size_t)(k+0)*(Dc/2) + j];
            float wb = W1[(size_t)(k+1)*(Dc/2) + j];
            float wc = W1[(size_t)(k+2)*(Dc/2) + j];
            float wd = W1[(size_t)(k+3)*(Dc/2) + j];
            float4 r0 = *(const float4*)&rfe[nb+0][k];
            float4 r1 = *(const float4*)&rfe[nb+1][k];
            float4 r2 = *(const float4*)&rfe[nb+2][k];
            float4 r3 = *(const float4*)&rfe[nb+3][k];
            acc0 += r0.x*wa + r0.y*wb + r0.z*wc + r0.w*wd;
            acc1 += r1.x*wa + r1.y*wb + r1.z*wc + r1.w*wd;
            acc2 += r2.x*wa + r2.y*wb + r2.z*wc + r2.w*wd;
            acc3 += r3.x*wa + r3.y*wb + r3.z*wc + r3.w*wd;
        }

        float wv = w2v_s[j];
        float p0 = ((acc0 >= 0.f) ? acc0 : 0.01f*acc0) * wv;
        float p1 = ((acc1 >= 0.f) ? acc1 : 0.01f*acc1) * wv;
        float p2 = ((acc2 >= 0.f) ? acc2 : 0.01f*acc2) * wv;
        float p3 = ((acc3 >= 0.f) ? acc3 : 0.01f*acc3) * wv;

        p0 = warp_sum(p0); p1 = warp_sum(p1); p2 = warp_sum(p2); p3 = warp_sum(p3);
        if (lane == 0) { red[warp][0]=p0; red[warp][1]=p1; red[warp][2]=p2; red[warp][3]=p3; }
        __syncthreads();
        if (t < NTH) {
            int n = t, hh = n >> 2, nn = n & 3;
            float s = red[hh*4+0][nn] + red[hh*4+1][nn] + red[hh*4+2][nn] + red[hh*4+3][nn];
            g_hisdot[slot0 + n] = s + c2_s;
        }
    } else {
        int wt = (blockIdx.x - NHIS) * 8 + warp;   // 0..263
        if (wt < Dc) {
            float s = warp_sum(dot8(W_proj + (size_t)wt*Dc + lane*8, w_ff + lane*8));
            if (lane == 0) g_u[wt] = s;
        } else if (wt < Dc + Bc) {
            int b   = wt - Dc;
            int cid = com_id[b];
            float th = theta[cid];
            float s = 0.f;
            #pragma unroll
            for (int i = 0; i < 8; i++) {
                int d = lane*8 + i;
                float m = (1.f - th) * company_emb[b*Dc + d] + th * comp_table[(size_t)cid*Dc + d];
                s += m * w_fc[d];
            }
            s = warp_sum(s);
            if (lane == 0) g_comp[b] = s + b_fc[0];
        } else if (wt == Dc + Bc) {
            float s = warp_sum(dot8(b_proj + lane*8, w_ff + lane*8));
            if (lane == 0) g_c0 = s;
        } else if (wt == Dc + Bc + 1) {
            if (lane == 0) g_done = 0;   // reset completion counter each replay
        }
    }
}

// ===========================================================================
// Kernel B: fused dense pass + sparse corrections.
//   Dense blocks [0, NMAIN): 32 rows via cp.async -> smem, 4 stages of 8
//   rows, ALL stages issued up front (32KB in flight/block, zero register
//   pressure) then computed stage-by-stage (warp-per-row from smem).
//   Corr blocks [NMAIN, +96): computed concurrently; tight-spin on g_done
//   only before the final store (WAW ordering). Deterministic.
// ===========================================================================
__global__ void __launch_bounds__(256) fused_kernel(
                            const float* __restrict__ field_table,
                            const float* __restrict__ field_emb,
                            const float* __restrict__ alpha_fields,
                            const float* __restrict__ w_ff,
                            const float* __restrict__ b_ff,
                            const int*   __restrict__ now_nodes,
                            const int*   __restrict__ his_nodes,
                            float* __restrict__ out)
{
    int t = threadIdx.x;
    int warp = t >> 5, lane = t & 31;

    if (blockIdx.x < NMAIN) {
        // ---------------- dense branch ----------------
        __shared__ __align__(16) float tile[MROWS * Dc];   // 32 KB
        const int row0 = blockIdx.x * MROWS;
        unsigned int tile_u32 = (unsigned int)__cvta_generic_to_shared(tile);

        // Issue ALL 4 stages (8 rows = 8KB each) as cp.async groups up front.
        #pragma unroll
        for (int s = 0; s < 4; s++) {
            #pragma unroll
            for (int k = 0; k < 2; k++) {
                int idx = t + k * 256;          // float4 index within stage, 0..511
                int r   = idx >> 6;             // row in stage 0..7
                int c4  = idx & 63;             // float4 column
                int gr  = row0 + s * 8 + r;
                if (gr >= Fc) gr = Fc - 1;      // clamp loads; stores guarded
                const float4* src = (const float4*)(field_table + (size_t)gr * Dc) + c4;
                unsigned int dst = tile_u32 + (unsigned int)(((s * 8 + r) * 64 + c4) * 16);
                asm volatile("cp.async.cg.shared.global [%0], [%1], 16;\n"
                             :: "r"(dst), "l"(src));
            }
            asm volatile("cp.async.commit_group;\n" ::: "memory");
        }

        // u slice + additive constants in registers (read while loads fly)
        float4 u0 = ((const float4*)g_u)[lane * 2];
        float4 u1 = ((const float4*)g_u)[lane * 2 + 1];
        float addb = (lane < Bc) ? (g_comp[lane] + b_ff[0] + g_c0) : 0.f;

        // Compute stage-by-stage: warp w owns row (stage*8 + w).
        #define DENSE_STAGE(S, WAITN)                                          \
        {                                                                      \
            asm volatile("cp.async.wait_group " #WAITN ";\n" ::: "memory");    \
            __syncthreads();                                                   \
            int f = row0 + S * 8 + warp;                                       \
            const float* rowp = tile + (S * 8 + warp) * Dc;                    \
            float4 v0 = *(const float4*)(rowp + lane * 8);                     \
            float4 v1 = *(const float4*)(rowp + lane * 8 + 4);                 \
            float acc = v0.x*u0.x + v0.y*u0.y + v0.z*u0.z + v0.w*u0.w          \
                      + v1.x*u1.x + v1.y*u1.y + v1.z*u1.z + v1.w*u1.w;         \
            acc = warp_sum(acc);                                               \
            if (lane < Bc && f < Fc)                                           \
                out[(size_t)lane * Fc + f] = acc + addb;                       \
        }
        DENSE_STAGE(0, 3)
        DENSE_STAGE(1, 2)
        DENSE_STAGE(2, 1)
        DENSE_STAGE(3, 0)
        #undef DENSE_STAGE

        // release: stores visible before counting this block done
        __threadfence();
        __syncthreads();
        if (t == 0) atomicAdd(&g_done, 1);
    } else {
        // ---------------- corr branch ----------------
        __shared__ __align__(16) float u_s[Dc];
        __shared__ __align__(16) float wff_s[Dc];
        __shared__ int now_s[KNc], his_s[KHc];
        int cid = blockIdx.x - NMAIN;      // 0..95
        int b   = cid / ((KNc + KHc)/8);   // 0..3
        int xb  = cid % ((KNc + KHc)/8);   // 0..23

        u_s[t]   = g_u[t];
        wff_s[t] = w_ff[t];
        if (t < KNc) now_s[t] = now_nodes[b*KNc + t];
        if (t < KHc) his_s[t] = his_nodes[b*KHc + t];
        __syncthreads();

        float cb = g_comp[b] + b_ff[0];
        float c0 = g_c0;

        int node = xb * 8 + warp;          // 0 .. 191
        int f = (node < KNc) ? now_s[node] : his_s[node - KNc];

        float a1 = dot8(field_table + (size_t)f*Dc + lane*8, u_s   + lane*8);
        float a2 = dot8(field_emb   + (size_t)f*Dc + lane*8, wff_s + lane*8);
        a1 = warp_sum(a1);
        a2 = warp_sum(a2);

        bool inNow = (now_s[lane] == f) || (now_s[lane + 32] == f);
        unsigned mN = __ballot_sync(0xffffffffu, inNow);

        int jmin = INT_MAX;
        #pragma unroll
        for (int r = 0; r < 4; r++) {
            int j = lane + r*32;
            if (his_s[j] == f && j < jmin) jmin = j;
        }
        #pragma unroll
        for (int o = 16; o > 0; o >>= 1) {
            int oth = __shfl_xor_sync(0xffffffffu, jmin, o);
            jmin = min(jmin, oth);
        }

        float alpha = alpha_fields[f];
        float val = (1.f - alpha) * (a1 + c0) + cb;
        if (mN)              val += alpha * a2;
        if (jmin != INT_MAX) val += alpha * g_hisdot[b*KHc + jmin];

        if (lane == 0) {
            // acquire: tight spin until ALL dense blocks done, then overwrite
            // (set semantics; duplicate (b,f) writers store identical bits)
            volatile int* p = &g_done;
            while (*p < NMAIN) { }
            __threadfence();
            out[(size_t)b*Fc + f] = val;
        }
    }
}

// ---------------------------------------------------------------------------
extern "C" void kernel_launch(void* const* d_in, const int* in_sizes, int n_in,
                              void* d_out, int out_size)
{
    const float* company_emb     = (const float*)d_in[0];
    const float* field_emb       = (const float*)d_in[1];
    const float* raw_field_embed = (const float*)d_in[2];
    const float* comp_table      = (const float*)d_in[3];
    const float* field_table     = (const float*)d_in[4];
    const float* W_proj          = (const float*)d_in[5];
    const float* b_proj          = (const float*)d_in[6];
    const float* theta           = (const float*)d_in[7];
    const float* alpha_fields    = (const float*)d_in[8];
    const float* w_ff            = (const float*)d_in[9];
    const float* b_ff            = (const float*)d_in[10];
    const float* w_fc            = (const float*)d_in[11];
    const float* b_fc            = (const float*)d_in[12];
    const float* W1              = (const float*)d_in[13];
    const float* b1              = (const float*)d_in[14];
    const float* W2              = (const float*)d_in[15];
    const float* b2              = (const float*)d_in[16];
    const int*   now_nodes       = (const int*)d_in[17];
    const int*   his_nodes       = (const int*)d_in[18];
    const int*   com_id          = (const int*)d_in[19];
    float* out = (float*)d_out;

    hisprep_kernel<<<NHIS + 33, 256>>>(raw_field_embed, W1, b1, W2, b2, w_ff,
                                       company_emb, comp_table, W_proj, b_proj,
                                       theta, w_fc, b_fc, com_id, his_nodes);
    fused_kernel<<<NMAIN + NCORR, 256>>>(field_table, field_emb, alpha_fields,
                                         w_ff, b_ff, now_nodes, his_nodes, out);
}

// round 10
// speedup vs baseline: 1.4394x; 1.4394x over previous
#include <cuda_runtime.h>
#include <cstdint>
#include <climits>

#define Bc 4
#define Fc 60082
#define Cc 14695
#define Dc 256
#define KNc 64
#define KHc 128
#define NTH 8                     // his slots per his block
#define MROWS 64                  // field rows per dense block (2 passes of 32)
#define NPREPB 33                 // prep blocks (33*8 = 264 >= 261 warp tasks)
#define NHIS ((Bc*KHc)/NTH)       // 64 his blocks
#define NCORR ((KNc + KHc) / 8 * Bc)        // 96 corr blocks
#define NMAIN ((Fc + MROWS - 1) / MROWS)    // 939 dense blocks
#define SMEM_BYTES 8960

// Scratch (no allocation allowed) — __device__ globals.
__device__ __align__(16) float g_u[Dc];   // W_proj @ w_ff
__device__ float g_comp[Bc];              // company_mem . w_fc + b_fc
__device__ float g_c0;                    // b_proj . w_ff
__device__ float g_hisdot[Bc*KHc];        // leaky(rfe@W1+b1).w2v + c2 per his slot
__device__ int   g_prep_done;             // 33 when prep finished
__device__ int   g_his_done;              // 64 when his finished
__device__ int   g_done;                  // NMAIN when dense finished
__device__ int   g_corr_done;             // 96 when corr finished (last resets all)

__device__ __forceinline__ float warp_sum(float v) {
    v += __shfl_xor_sync(0xffffffffu, v, 16);
    v += __shfl_xor_sync(0xffffffffu, v, 8);
    v += __shfl_xor_sync(0xffffffffu, v, 4);
    v += __shfl_xor_sync(0xffffffffu, v, 2);
    v += __shfl_xor_sync(0xffffffffu, v, 1);
    return v;
}

__device__ __forceinline__ float dot8(const float* __restrict__ a, const float* __restrict__ b) {
    float4 a0 = ((const float4*)a)[0], a1 = ((const float4*)a)[1];
    float4 b0 = ((const float4*)b)[0], b1 = ((const float4*)b)[1];
    return a0.x*b0.x + a0.y*b0.y + a0.z*b0.z + a0.w*b0.w
         + a1.x*b1.x + a1.y*b1.y + a1.z*b1.z + a1.w*b1.w;
}

__device__ __forceinline__ void spin_until(int* ctr, int target, unsigned ns) {
    volatile int* p = ctr;
    while (*p < target) { __nanosleep(ns); }
}

// ===========================================================================
// ONE kernel. Block-id layout (low ids launch first → wave-1 residents):
//   [0, 33)        prep   : g_u, g_comp, g_c0            -> g_prep_done
//   [33, 97)       his    : g_hisdot (local w2v/c2)      -> g_his_done
//   [97, 193)      corr   : gathers early, stores last   -> g_corr_done
//   [193, 193+939) dense  : streams field_table          -> g_done
// corr overwrites touched rows AFTER g_done==NMAIN (WAW set semantics).
// Last corr block resets all counters for the next graph replay.
// ===========================================================================
__global__ void __launch_bounds__(256) mega_kernel(
                            const float* __restrict__ field_table,
                            const float* __restrict__ field_emb,
                            const float* __restrict__ raw_field_embed,
                            const float* __restrict__ alpha_fields,
                            const float* __restrict__ w_ff,
                            const float* __restrict__ b_ff,
                            const float* __restrict__ W1,
                            const float* __restrict__ b1,
                            const float* __restrict__ W2,
                            const float* __restrict__ b2,
                            const float* __restrict__ W_proj,
                            const float* __restrict__ b_proj,
                            const float* __restrict__ theta,
                            const float* __restrict__ w_fc,
                            const float* __restrict__ b_fc,
                            const float* __restrict__ company_emb,
                            const float* __restrict__ comp_table,
                            const int*   __restrict__ com_id,
                            const int*   __restrict__ now_nodes,
                            const int*   __restrict__ his_nodes,
                            float* __restrict__ out)
{
    __shared__ __align__(16) unsigned char smraw[SMEM_BYTES];
    int t = threadIdx.x;
    int warp = t >> 5, lane = t & 31;
    int bid = blockIdx.x;

    if (bid < NPREPB) {
        // ======================= prep =======================
        int wt = bid * 8 + warp;   // 0..263
        if (wt < Dc) {
            float s = warp_sum(dot8(W_proj + (size_t)wt*Dc + lane*8, w_ff + lane*8));
            if (lane == 0) g_u[wt] = s;
        } else if (wt < Dc + Bc) {
            int b   = wt - Dc;
            int cid = com_id[b];
            float th = theta[cid];
            float s = 0.f;
            #pragma unroll
            for (int i = 0; i < 8; i++) {
                int d = lane*8 + i;
                float m = (1.f - th) * company_emb[b*Dc + d] + th * comp_table[(size_t)cid*Dc + d];
                s += m * w_fc[d];
            }
            s = warp_sum(s);
            if (lane == 0) g_comp[b] = s + b_fc[0];
        } else if (wt == Dc + Bc) {
            float s = warp_sum(dot8(b_proj + lane*8, w_ff + lane*8));
            if (lane == 0) g_c0 = s;
        }
        __syncthreads();
        if (t == 0) { __threadfence(); atomicAdd(&g_prep_done, 1); }

    } else if (bid < NPREPB + NHIS) {
        // ======================= his =======================
        float (*rfe)[Dc] = (float (*)[Dc])smraw;                   // 8192 B
        float (*red)[4]  = (float (*)[4])(smraw + 8192);           // 128 B
        float* w2v_s     = (float*)(smraw + 8320);                 // 512 B
        float* c2_s      = (float*)(smraw + 8832);                 // 4 B
        int j = t & 127, h = t >> 7;
        int slot0 = (bid - NPREPB) * NTH;

        #pragma unroll
        for (int i = t; i < NTH*Dc/4; i += 256) {
            int n  = i >> 6;
            int c4 = i & 63;
            int f  = his_nodes[slot0 + n];
            ((float4*)rfe[n])[c4] = ((const float4*)(raw_field_embed + (size_t)f*Dc))[c4];
        }
        #pragma unroll
        for (int r = 0; r < 16; r++) {
            int jr = warp * 16 + r;
            float s = warp_sum(dot8(W2 + (size_t)jr*Dc + lane*8, w_ff + lane*8));
            if (lane == 0) w2v_s[jr] = s;
        }
        if (warp == 0) {
            float s = warp_sum(dot8(b2 + lane*8, w_ff + lane*8));
            if (lane == 0) *c2_s = s;
        }
        __syncthreads();

        float bj = b1[j];
        float acc0 = bj, acc1 = bj, acc2 = bj, acc3 = bj;
        int nb = h * 4;
        #pragma unroll 4
        for (int k = 0; k < Dc; k += 4) {
            float wa = W1[(size_t)(k+0)*(Dc/2) + j];
            float wb = W1[(size_t)(k+1)*(Dc/2) + j];
            float wc = W1[(size_t)(k+2)*(Dc/2) + j];
            float wd = W1[(size_t)(k+3)*(Dc/2) + j];
            float4 r0 = *(const float4*)&rfe[nb+0][k];
            float4 r1 = *(const float4*)&rfe[nb+1][k];
            float4 r2 = *(const float4*)&rfe[nb+2][k];
            float4 r3 = *(const float4*)&rfe[nb+3][k];
            acc0 += r0.x*wa + r0.y*wb + r0.z*wc + r0.w*wd;
            acc1 += r1.x*wa + r1.y*wb + r1.z*wc + r1.w*wd;
            acc2 += r2.x*wa + r2.y*wb + r2.z*wc + r2.w*wd;
            acc3 += r3.x*wa + r3.y*wb + r3.z*wc + r3.w*wd;
        }

        float wv = w2v_s[j];
        float p0 = ((acc0 >= 0.f) ? acc0 : 0.01f*acc0) * wv;
        float p1 = ((acc1 >= 0.f) ? acc1 : 0.01f*acc1) * wv;
        float p2 = ((acc2 >= 0.f) ? acc2 : 0.01f*acc2) * wv;
        float p3 = ((acc3 >= 0.f) ? acc3 : 0.01f*acc3) * wv;

        p0 = warp_sum(p0); p1 = warp_sum(p1); p2 = warp_sum(p2); p3 = warp_sum(p3);
        if (lane == 0) { red[warp][0]=p0; red[warp][1]=p1; red[warp][2]=p2; red[warp][3]=p3; }
        __syncthreads();
        if (t < NTH) {
            int n = t, hh = n >> 2, nn = n & 3;
            float s = red[hh*4+0][nn] + red[hh*4+1][nn] + red[hh*4+2][nn] + red[hh*4+3][nn];
            g_hisdot[slot0 + n] = s + *c2_s;
        }
        __syncthreads();
        if (t == 0) { __threadfence(); atomicAdd(&g_his_done, 1); }

    } else if (bid < NPREPB + NHIS + NCORR) {
        // ======================= corr =======================
        float* u_s   = (float*)smraw;             // 1024 B
        float* wff_s = (float*)(smraw + 1024);    // 1024 B
        int*   now_s = (int*)(smraw + 2048);      // 256 B
        int*   his_s = (int*)(smraw + 2304);      // 512 B
        int cid = bid - NPREPB - NHIS;     // 0..95
        int b   = cid / ((KNc + KHc)/8);   // 0..3
        int xb  = cid % ((KNc + KHc)/8);   // 0..23

        if (t == 0) spin_until(&g_prep_done, NPREPB, 300);
        __syncthreads();
        __threadfence();

        u_s[t]   = g_u[t];
        wff_s[t] = w_ff[t];
        if (t < KNc) now_s[t] = now_nodes[b*KNc + t];
        if (t < KHc) his_s[t] = his_nodes[b*KHc + t];
        __syncthreads();

        float cb = g_comp[b] + b_ff[0];
        float c0 = g_c0;

        int node = xb * 8 + warp;          // 0 .. 191
        int f = (node < KNc) ? now_s[node] : his_s[node - KNc];

        float a1 = dot8(field_table + (size_t)f*Dc + lane*8, u_s   + lane*8);
        float a2 = dot8(field_emb   + (size_t)f*Dc + lane*8, wff_s + lane*8);
        a1 = warp_sum(a1);
        a2 = warp_sum(a2);

        bool inNow = (now_s[lane] == f) || (now_s[lane + 32] == f);
        unsigned mN = __ballot_sync(0xffffffffu, inNow);

        int jmin = INT_MAX;
        #pragma unroll
        for (int r = 0; r < 4; r++) {
            int j = lane + r*32;
            if (his_s[j] == f && j < jmin) jmin = j;
        }
        #pragma unroll
        for (int o = 16; o > 0; o >>= 1) {
            int oth = __shfl_xor_sync(0xffffffffu, jmin, o);
            jmin = min(jmin, oth);
        }

        float alpha = alpha_fields[f];
        float val = (1.f - alpha) * (a1 + c0) + cb;
        if (mN) val += alpha * a2;

        if (lane == 0) {
            if (jmin != INT_MAX) {
                spin_until(&g_his_done, NHIS, 200);
                __threadfence();
                val += alpha * g_hisdot[b*KHc + jmin];
            }
            // wait for ALL dense blocks, then overwrite (set semantics;
            // duplicate (b,f) writers store identical bits)
            spin_until(&g_done, NMAIN, 200);
            __threadfence();
            out[(size_t)b*Fc + f] = val;
        }
        __syncthreads();
        if (t == 0) {
            __threadfence();
            int v = atomicAdd(&g_corr_done, 1);
            if (v == NCORR - 1) {   // last finisher resets counters for next replay
                g_prep_done = 0;
                g_his_done  = 0;
                g_done      = 0;
                g_corr_done = 0;
            }
        }

    } else {
        // ======================= dense =======================
        float4* u_s4 = (float4*)smraw;   // 1 KB
        int db = bid - NPREPB - NHIS - NCORR;   // 0..NMAIN-1

        if (t == 0) spin_until(&g_prep_done, NPREPB, 800);
        __syncthreads();
        __threadfence();

        if (t < Dc/4) u_s4[t] = ((const float4*)g_u)[t];
        __syncthreads();

        int grp = lane >> 3, sub = lane & 7;
        float addb = g_comp[lane & 3] + b_ff[0] + g_c0;
        int blockBase = db * MROWS;

        #pragma unroll
        for (int p = 0; p < 2; p++) {
            int r0 = blockBase + p * 32 + warp * 4;   // first of 4 rows this warp-pass
            int f  = r0 + grp;
            int fc = (f < Fc) ? f : (Fc - 1);         // clamp loads; stores guarded
            const float4* row = (const float4*)(field_table + (size_t)fc * Dc);

            float4 v[8];
            #pragma unroll
            for (int i = 0; i < 8; i++) v[i] = row[sub + 8*i];

            float acc = 0.f;
            #pragma unroll
            for (int i = 0; i < 8; i++) {
                float4 uu = u_s4[sub + 8*i];
                acc += v[i].x*uu.x + v[i].y*uu.y + v[i].z*uu.z + v[i].w*uu.w;
            }
            // reduce within 8-lane group
            acc += __shfl_xor_sync(0xffffffffu, acc, 4);
            acc += __shfl_xor_sync(0xffffffffu, acc, 2);
            acc += __shfl_xor_sync(0xffffffffu, acc, 1);
            // assemble the 4 group sums warp-wide
            float t1 = __shfl_xor_sync(0xffffffffu, acc, 8);
            float t2 = __shfl_xor_sync(0xffffffffu, acc, 16);
            float t3 = __shfl_xor_sync(0xffffffffu, t1, 16);

            if (lane < 8) {
                int b = lane & 3, h = lane >> 2;
                int fr = r0 + 2*h;
                if (fr < Fc) {          // Fc even & fr even -> pair fully in/out
                    float2 q;
                    q.x = (h ? t2 : acc) + addb;
                    q.y = (h ? t3 : t1)  + addb;
                    *(float2*)(out + (size_t)b*Fc + fr) = q;
                }
            }
        }

        // release: stores visible before counting this block done
        __threadfence();
        __syncthreads();
        if (t == 0) atomicAdd(&g_done, 1);
    }
}

// ---------------------------------------------------------------------------
extern "C" void kernel_launch(void* const* d_in, const int* in_sizes, int n_in,
                              void* d_out, int out_size)
{
    const float* company_emb     = (const float*)d_in[0];
    const float* field_emb       = (const float*)d_in[1];
    const float* raw_field_embed = (const float*)d_in[2];
    const float* comp_table      = (const float*)d_in[3];
    const float* field_table     = (const float*)d_in[4];
    const float* W_proj          = (const float*)d_in[5];
    const float* b_proj          = (const float*)d_in[6];
    const float* theta           = (const float*)d_in[7];
    const float* alpha_fields    = (const float*)d_in[8];
    const float* w_ff            = (const float*)d_in[9];
    const float* b_ff            = (const float*)d_in[10];
    const float* w_fc            = (const float*)d_in[11];
    const float* b_fc            = (const float*)d_in[12];
    const float* W1              = (const float*)d_in[13];
    const float* b1              = (const float*)d_in[14];
    const float* W2              = (const float*)d_in[15];
    const float* b2              = (const float*)d_in[16];
    const int*   now_nodes       = (const int*)d_in[17];
    const int*   his_nodes       = (const int*)d_in[18];
    const int*   com_id          = (const int*)d_in[19];
    float* out = (float*)d_out;

    mega_kernel<<<NPREPB + NHIS + NCORR + NMAIN, 256>>>(
        field_table, field_emb, raw_field_embed, alpha_fields, w_ff, b_ff,
        W1, b1, W2, b2, W_proj, b_proj, theta, w_fc, b_fc,
        company_emb, comp_table, com_id, now_nodes, his_nodes, out);
}